// round 15
// baseline (speedup 1.0000x reference)
#include <cuda_runtime.h>
#include <math.h>

#define BT    64
#define NPIX  49
#define CDIM  2048
#define VOCAB 10000
#define DSPLIT 32
#define KS    8    // k-split for 512-K GEMMs
#define SKS   4    // k-split for scores

// ---------------- scratch ----------------
__device__ float g_prep[KS*2*BT*512];
__device__ float g_hgatep[KS*2*BT*512];
__device__ float g_sgatep[KS*2*BT*512];
__device__ float g_s[BT*512];
__device__ float g_alpha0[BT*CDIM];
__device__ float g_stats[BT*2];          // per-bt softmax (m2, inv)
__device__ float g_Mpart[DSPLIT*BT*NPIX*NPIX];
__device__ float g_Msum[BT*NPIX*NPIX];
__device__ float g_cchanp[DSPLIT*BT*NPIX];
__device__ float g_cspat[BT*CDIM];
__device__ float g_spart[16*BT*512];
__device__ float g_chat[BT*512];
__device__ float g_scorep[SKS*BT*VOCAB];

__device__ __forceinline__ float tanh_fast(float x) {
    float y;
    asm("tanh.approx.f32 %0, %1;" : "=f"(y) : "f"(x));
    return y;
}
__device__ __forceinline__ float sigmoidf_(float x) {
    return 1.0f / (1.0f + __expf(-x));
}

// ---------------------------------------------------------------------------
// bigA: op0: x@Wsx + hprev@Wsh ; op1: h@Wg2 ; op2: h@Wghs ; op3: h@Wghc.
// grid (4, 32, 4) = 512 blocks, 256 thr; K=64/block; float4 weights.
// ---------------------------------------------------------------------------
__global__ void bigA_kernel(const float* __restrict__ x,
                            const float* __restrict__ hiddens,
                            const float* __restrict__ Wsx,
                            const float* __restrict__ Wsh,
                            const float* __restrict__ Wg2,
                            const float* __restrict__ Wghs,
                            const float* __restrict__ Wghc) {
    __shared__ __align__(16) float As[16][64];
    const int op = blockIdx.z;
    const int ks = blockIdx.y >> 2;
    const int m0 = (blockIdx.y & 3) * 16;
    const int n0 = blockIdx.x * 128;
    const int k0 = ks * 64;
    const int col = n0 + (threadIdx.x & 31) * 4;
    const int rl  = (threadIdx.x >> 5) * 2;
    const int r0  = m0 + rl;
    float4 acc0 = {0.f,0.f,0.f,0.f}, acc1 = {0.f,0.f,0.f,0.f};
    const int nph = (op == 0) ? 2 : 1;
    for (int phase = 0; phase < nph; ++phase) {
        const float* W = (op == 0) ? (phase ? Wsh : Wsx)
                       : (op == 1) ? Wg2 : (op == 2) ? Wghs : Wghc;
        __syncthreads();
        for (int i = threadIdx.x; i < 1024; i += 256) {
            int r = m0 + (i >> 6), kk = i & 63;
            float v;
            if (op == 0 && phase == 1) v = (r & 7) ? hiddens[(r - 1) * 512 + k0 + kk] : 0.f;
            else if (op == 0)          v = x[r * 512 + k0 + kk];
            else                       v = hiddens[r * 512 + k0 + kk];
            As[i >> 6][kk] = v;
        }
        __syncthreads();
        #pragma unroll 8
        for (int kk = 0; kk < 64; kk++) {
            const float4 w = *reinterpret_cast<const float4*>(&W[(size_t)(k0 + kk) * 512 + col]);
            float a0 = As[rl][kk], a1 = As[rl + 1][kk];
            acc0.x += a0 * w.x; acc0.y += a0 * w.y; acc0.z += a0 * w.z; acc0.w += a0 * w.w;
            acc1.x += a1 * w.x; acc1.y += a1 * w.y; acc1.z += a1 * w.z; acc1.w += a1 * w.w;
        }
    }
    float* dst = (op < 2) ? g_prep : g_hgatep;
    const int o2 = op & 1;
    *reinterpret_cast<float4*>(&dst[((ks*2 + o2)*BT + r0)*512 + col])     = acc0;
    *reinterpret_cast<float4*>(&dst[((ks*2 + o2)*BT + r0 + 1)*512 + col]) = acc1;
}

// ---------------------------------------------------------------------------
// s_finalize: g_s = sigmoid(sum partials) * tanh(cells).  64 x 512.
// ---------------------------------------------------------------------------
__global__ void s_finalize_kernel(const float* __restrict__ cells) {
    const int r = blockIdx.x, c = threadIdx.x;
    float p = 0.f;
    #pragma unroll
    for (int ks = 0; ks < KS; ks++) p += g_prep[((ks*2 + 0)*BT + r)*512 + c];
    g_s[r*512 + c] = sigmoidf_(p) * tanh_fast(cells[r*512 + c]);
}

// ---------------------------------------------------------------------------
// cxtgates: merged launch. blocks 0..255: cxt; blocks 256..511: gatesS.
// ---------------------------------------------------------------------------
__global__ void cxtgates_kernel(const float* __restrict__ V,
                                const float* __restrict__ Wfeat,
                                const float* __restrict__ Wcxt,
                                const float* __restrict__ Wgvs,
                                const float* __restrict__ Wgvc) {
    __shared__ __align__(16) float sm0[512];
    __shared__ __align__(16) float sm1[512];
    __shared__ __align__(16) float sm2[512];
    const int bx = blockIdx.x;
    const int t = threadIdx.x;
    if (bx < 256) {
        float* wf = sm0; float* wc = sm1; float* gr = sm2;
        const int bt = bx >> 2, b = bt >> 3, chunk = bx & 3;
        for (int i = t; i < 512; i += 256) {
            wf[i] = Wfeat[i];
            wc[i] = Wcxt[i];
            float g = 0.f;
            #pragma unroll
            for (int ks = 0; ks < KS; ks++) g += g_prep[((ks*2 + 1)*BT + bt)*512 + i];
            gr[i] = g;
        }
        const int d0 = chunk * 512 + t;
        float a0s = 0.f, a1s = 0.f;
        #pragma unroll 7
        for (int k = 0; k < NPIX; k++) {
            a0s += V[(b * NPIX + k) * CDIM + d0];
            a1s += V[(b * NPIX + k) * CDIM + d0 + 256];
        }
        const float a0 = a0s * (1.0f / 49.0f);
        const float a1 = a1s * (1.0f / 49.0f);
        __syncthreads();
        float c0 = 0.f, c1 = 0.f;
        #pragma unroll 4
        for (int j = 0; j < 512; j++) {
            float wfj = wf[j], grj = gr[j], wcj = wc[j];
            c0 += tanh_fast(fmaf(a0, wfj, grj)) * wcj;
            c1 += tanh_fast(fmaf(a1, wfj, grj)) * wcj;
        }
        g_alpha0[bt * CDIM + d0]       = c0;
        g_alpha0[bt * CDIM + d0 + 256] = c1;
    } else {
        float (*As)[64] = reinterpret_cast<float (*)[64]>(sm0);
        const int g = bx - 256;
        const int op = g >> 7;
        const int rem = g & 127;
        const int colTile = rem & 3;
        const int ry = rem >> 2;
        const int ks = ry >> 2;
        const int m0 = (ry & 3) * 16;
        const int n0 = colTile * 128;
        const int k0 = ks * 64;
        const int col = n0 + (t & 31) * 4;
        const int rl  = (t >> 5) * 2;
        const int r0  = m0 + rl;
        const float* W = op ? Wgvc : Wgvs;
        for (int i = t; i < 1024; i += 256) {
            int r = m0 + (i >> 6), kk = i & 63;
            As[i >> 6][kk] = g_s[r * 512 + k0 + kk];
        }
        __syncthreads();
        float4 acc0 = {0.f,0.f,0.f,0.f}, acc1 = {0.f,0.f,0.f,0.f};
        #pragma unroll 8
        for (int kk = 0; kk < 64; kk++) {
            const float4 w = *reinterpret_cast<const float4*>(&W[(size_t)(k0 + kk) * 512 + col]);
            float a0 = As[rl][kk], a1 = As[rl + 1][kk];
            acc0.x += a0 * w.x; acc0.y += a0 * w.y; acc0.z += a0 * w.z; acc0.w += a0 * w.w;
            acc1.x += a1 * w.x; acc1.y += a1 * w.y; acc1.z += a1 * w.z; acc1.w += a1 * w.w;
        }
        *reinterpret_cast<float4*>(&g_sgatep[((ks*2 + op)*BT + r0)*512 + col])     = acc0;
        *reinterpret_cast<float4*>(&g_sgatep[((ks*2 + op)*BT + r0 + 1)*512 + col]) = acc1;
    }
}

// ---------------------------------------------------------------------------
// smstats: per-bt softmax stats (max, 1/sum).  64 blocks x 256.
// ---------------------------------------------------------------------------
__global__ void smstats_kernel() {
    __shared__ float red[256];
    const int bt = blockIdx.x, t = threadIdx.x;
    const float* p = g_alpha0 + bt * CDIM;
    float mx = -1e30f;
    for (int i = t; i < CDIM; i += 256) mx = fmaxf(mx, p[i]);
    red[t] = mx; __syncthreads();
    for (int s = 128; s > 0; s >>= 1) { if (t < s) red[t] = fmaxf(red[t], red[t + s]); __syncthreads(); }
    mx = red[0]; __syncthreads();
    float sm = 0.f;
    for (int i = t; i < CDIM; i += 256) sm += __expf(p[i] - mx);
    red[t] = sm; __syncthreads();
    for (int s = 128; s > 0; s >>= 1) { if (t < s) red[t] += red[t + s]; __syncthreads(); }
    if (t == 0) {
        g_stats[bt * 2]     = mx;
        g_stats[bt * 2 + 1] = 1.0f / red[0];
    }
}

// ---------------------------------------------------------------------------
// wfwv: 8x8 register tiles, 64 thr, K=64/block.  grid (64 bt, 32 dp).
// threads 0..48 compute M; 49..63 do cchan row sums; all stage.
// smem ~28KB -> 8 blocks/SM.
// ---------------------------------------------------------------------------
__global__ void wfwv_kernel(const float* __restrict__ V,
                            const float* __restrict__ Wv) {
    __shared__ __align__(16) float Wvs[64][56];   // rows 224B: 16B-aligned
    __shared__ __align__(16) float aV[49][69];    // odd-ish stride: <=2-way conflicts
    __shared__ __align__(16) float alp[64];
    const int bt = blockIdx.x, b = bt >> 3;
    const int dp = blockIdx.y, d0 = dp * 64;
    const int t = threadIdx.x;

    const float m2  = g_stats[bt * 2];
    const float inv = g_stats[bt * 2 + 1];
    alp[t] = __expf(g_alpha0[bt * CDIM + d0 + t] - m2) * inv;
    __syncthreads();

    // stage aV = V*alpha and Wvs (one barrier)
    for (int i = t; i < 49 * 64; i += 64) {
        int r = i >> 6, dd = i & 63;
        aV[r][dd] = V[(b * NPIX + r) * CDIM + d0 + dd] * alp[dd];
    }
    for (int i = t; i < 64 * 49; i += 64) {
        int dd = i / 49, k2 = i % 49;
        Wvs[dd][k2] = Wv[(size_t)(d0 + dd) * NPIX + k2];
    }
    for (int i = t; i < 64 * 7; i += 64) Wvs[i / 7][49 + (i % 7)] = 0.f;
    __syncthreads();

    if (t < 49) {
        const int tr = t / 7, tc = t % 7;
        int ri[8];
        #pragma unroll
        for (int i = 0; i < 8; i++) ri[i] = min(tr * 8 + i, 48);
        float acc[8][8];
        #pragma unroll
        for (int i = 0; i < 8; i++)
            #pragma unroll
            for (int j = 0; j < 8; j++) acc[i][j] = 0.f;
        #pragma unroll 2
        for (int dd = 0; dd < 64; dd++) {
            const float4 w0 = *reinterpret_cast<const float4*>(&Wvs[dd][tc * 8]);
            const float4 w1 = *reinterpret_cast<const float4*>(&Wvs[dd][tc * 8 + 4]);
            float av[8];
            #pragma unroll
            for (int i = 0; i < 8; i++) av[i] = aV[ri[i]][dd];
            #pragma unroll
            for (int i = 0; i < 8; i++) {
                acc[i][0] += av[i] * w0.x; acc[i][1] += av[i] * w0.y;
                acc[i][2] += av[i] * w0.z; acc[i][3] += av[i] * w0.w;
                acc[i][4] += av[i] * w1.x; acc[i][5] += av[i] * w1.y;
                acc[i][6] += av[i] * w1.z; acc[i][7] += av[i] * w1.w;
            }
        }
        float* mp = g_Mpart + ((size_t)dp * BT + bt) * NPIX * NPIX;
        #pragma unroll
        for (int i = 0; i < 8; i++) {
            int k = tr * 8 + i;
            if (k >= NPIX) break;
            #pragma unroll
            for (int j = 0; j < 8; j++) {
                int k2 = tc * 8 + j;
                if (k2 < NPIX) mp[k * NPIX + k2] = acc[i][j];
            }
        }
    } else {
        // cchan: rows t-49, +15, +30, +45
        const int r0 = t - 49;
        float s0 = 0.f, s1 = 0.f, s2 = 0.f, s3 = 0.f;
        #pragma unroll 8
        for (int dd = 0; dd < 64; dd++) {
            s0 += aV[r0][dd];
            if (r0 + 15 < NPIX) s1 += aV[r0 + 15][dd];
            if (r0 + 30 < NPIX) s2 += aV[r0 + 30][dd];
            if (r0 + 45 < NPIX) s3 += aV[r0 + 45][dd];
        }
        float* cp = g_cchanp + (dp * BT + bt) * NPIX;
        cp[r0] = s0;
        if (r0 + 15 < NPIX) cp[r0 + 15] = s1;
        if (r0 + 30 < NPIX) cp[r0 + 30] = s2;
        if (r0 + 45 < NPIX) cp[r0 + 45] = s3;
    }
}

// ---------------------------------------------------------------------------
// mreduce: Msum = sum over 32 Mpart slices.  601 blocks x 256.
// ---------------------------------------------------------------------------
__global__ void mreduce_kernel() {
    const int idx = blockIdx.x * 256 + threadIdx.x;
    if (idx >= BT * NPIX * NPIX) return;
    const size_t stride = (size_t)BT * NPIX * NPIX;
    float v = 0.f;
    #pragma unroll
    for (int p = 0; p < DSPLIT; p++) v += g_Mpart[p * stride + idx];
    g_Msum[idx] = v;
}

// ---------------------------------------------------------------------------
// zt: fused gcs + z_t + softmaxes + c_spatial. grid 64 x 256 thr.
// ---------------------------------------------------------------------------
__global__ void zt_kernel(const float* __restrict__ hiddens,
                          const float* __restrict__ V,
                          const float* __restrict__ Wg,
                          const float* __restrict__ Ws,
                          const float* __restrict__ Wh,
                          float* __restrict__ out_alpha,
                          float* __restrict__ out_beta) {
    __shared__ float h_sm[512], s_sm[512];
    __shared__ float Msum[NPIX * NPIX];
    __shared__ float pg[8][NPIX], ps[8][NPIX];
    __shared__ float gg[NPIX], css[NPIX], wh[NPIX], ztv[NPIX], al[NPIX];
    const int bt = blockIdx.x, b = bt >> 3, t = threadIdx.x;
    for (int i = t; i < 512; i += 256) {
        h_sm[i] = hiddens[bt * 512 + i];
        s_sm[i] = g_s[bt * 512 + i];
    }
    if (t < NPIX) wh[t] = Wh[t];
    for (int i = t; i < NPIX * NPIX; i += 256)
        Msum[i] = g_Msum[bt * NPIX * NPIX + i];
    __syncthreads();
    {
        const int w = t >> 5, lane = t & 31;
        float gp0 = 0.f, sp0 = 0.f, gp1 = 0.f, sp1 = 0.f;
        const int j1 = lane + 32;
        for (int kk = 0; kk < 64; kk++) {
            int k = w * 64 + kk;
            float hk = h_sm[k], sk = s_sm[k];
            gp0 += hk * Wg[k * NPIX + lane];
            sp0 += sk * Ws[k * NPIX + lane];
            if (j1 < NPIX) {
                gp1 += hk * Wg[k * NPIX + j1];
                sp1 += sk * Ws[k * NPIX + j1];
            }
        }
        pg[w][lane] = gp0; ps[w][lane] = sp0;
        if (j1 < NPIX) { pg[w][j1] = gp1; ps[w][j1] = sp1; }
    }
    __syncthreads();
    if (t < NPIX) {
        float gv = 0.f, sv = 0.f;
        #pragma unroll
        for (int w = 0; w < 8; w++) { gv += pg[w][t]; sv += ps[w][t]; }
        gg[t] = gv;
        css[t] = sv + gv;
    }
    __syncthreads();
    if (t < NPIX) {
        float z = 0.f;
        #pragma unroll 7
        for (int k2 = 0; k2 < NPIX; k2++)
            z += tanh_fast(tanh_fast(Msum[t * NPIX + k2] + gg[k2])) * wh[k2];
        ztv[t] = z;
    }
    __syncthreads();
    if (t == 0) {
        float ze = 0.f;
        for (int k = 0; k < NPIX; k++) ze += tanh_fast(css[k]) * wh[k];
        float mx = -1e30f;
        for (int k = 0; k < NPIX; k++) mx = fmaxf(mx, ztv[k]);
        float sm = 0.f;
        for (int k = 0; k < NPIX; k++) sm += __expf(ztv[k] - mx);
        float inv = 1.0f / sm;
        for (int k = 0; k < NPIX; k++) {
            float a = __expf(ztv[k] - mx) * inv;
            al[k] = a;
            out_alpha[bt * NPIX + k] = a;
        }
        float mx2 = fmaxf(mx, ze);
        float sm2 = 0.f;
        for (int k = 0; k < NPIX; k++) sm2 += __expf(ztv[k] - mx2);
        sm2 += __expf(ze - mx2);
        out_beta[bt] = __expf(ze - mx2) / sm2;
    }
    __syncthreads();
    for (int d = t; d < CDIM; d += 256) {
        float s = 0.f;
        #pragma unroll 7
        for (int k = 0; k < NPIX; k++) s += al[k] * V[(b * NPIX + k) * CDIM + d];
        g_cspat[bt * CDIM + d] = s;
    }
}

// ---------------------------------------------------------------------------
// spatpart: cspat@Wspat partials, K-split 16. grid (4, 64), 256 thr.
// ---------------------------------------------------------------------------
__global__ void spatpart_kernel(const float* __restrict__ Wspat) {
    __shared__ __align__(16) float As[16][64];
    const int ks = blockIdx.y >> 2;
    const int m0 = (blockIdx.y & 3) * 16;
    const int n0 = blockIdx.x * 128;
    const int kbase = ks * 128;
    const int col = n0 + (threadIdx.x & 31) * 4;
    const int rl  = (threadIdx.x >> 5) * 2;
    const int r0  = m0 + rl;
    float4 acc0 = {0.f,0.f,0.f,0.f}, acc1 = {0.f,0.f,0.f,0.f};
    for (int k0 = kbase; k0 < kbase + 128; k0 += 64) {
        __syncthreads();
        for (int i = threadIdx.x; i < 1024; i += 256) {
            int r = m0 + (i >> 6), kk = i & 63;
            As[i >> 6][kk] = g_cspat[r * CDIM + k0 + kk];
        }
        __syncthreads();
        #pragma unroll 8
        for (int kk = 0; kk < 64; kk++) {
            const float4 w = *reinterpret_cast<const float4*>(&Wspat[(size_t)(k0 + kk) * 512 + col]);
            float a0 = As[rl][kk], a1 = As[rl + 1][kk];
            acc0.x += a0 * w.x; acc0.y += a0 * w.y; acc0.z += a0 * w.z; acc0.w += a0 * w.w;
            acc1.x += a1 * w.x; acc1.y += a1 * w.y; acc1.z += a1 * w.z; acc1.w += a1 * w.w;
        }
    }
    *reinterpret_cast<float4*>(&g_spart[(ks * BT + r0) * 512 + col])     = acc0;
    *reinterpret_cast<float4*>(&g_spart[(ks * BT + r0 + 1) * 512 + col]) = acc1;
}

// ---------------------------------------------------------------------------
// combine: chat = sig(gates)*spat + sig(gates)*cchan@Wchan + h.  64 x 512.
// ---------------------------------------------------------------------------
__global__ void combine_kernel(const float* __restrict__ hiddens,
                               const float* __restrict__ Wchan) {
    __shared__ float ch[NPIX];
    const int r = blockIdx.x, c = threadIdx.x;
    if (c < NPIX) {
        float v = 0.f;
        #pragma unroll
        for (int p = 0; p < DSPLIT; p++) v += g_cchanp[(p * BT + r) * NPIX + c];
        ch[c] = v * (1.0f / 2048.0f);
    }
    __syncthreads();
    float spat = 0.f;
    #pragma unroll
    for (int p = 0; p < 16; p++) spat += g_spart[(p * BT + r) * 512 + c];
    float sg = 0.f, cg = 0.f;
    #pragma unroll
    for (int ks = 0; ks < KS; ks++) {
        sg += g_sgatep[((ks*2 + 0)*BT + r)*512 + c] + g_hgatep[((ks*2 + 0)*BT + r)*512 + c];
        cg += g_sgatep[((ks*2 + 1)*BT + r)*512 + c] + g_hgatep[((ks*2 + 1)*BT + r)*512 + c];
    }
    float cb = 0.f;
    #pragma unroll 7
    for (int k = 0; k < NPIX; k++) cb += ch[k] * Wchan[k * 512 + c];
    g_chat[r * 512 + c] = sigmoidf_(sg) * spat
                        + sigmoidf_(cg) * cb
                        + hiddens[r * 512 + c];
}

// ---------------------------------------------------------------------------
// scores partials: grid (79, 4) = 316 blocks, 256 thr, K=128/block.
// ---------------------------------------------------------------------------
__global__ void scores_kernel(const float* __restrict__ Wmlp) {
    __shared__ __align__(16) float As[64][33];
    const int n0 = blockIdx.x * 128;
    const int ks = blockIdx.y;
    const int kbase = ks * 128;
    const int rowg = threadIdx.x >> 5;
    const int colg = threadIdx.x & 31;
    const int c0 = n0 + colg * 4;
    const bool okfull = (c0 + 3 < VOCAB);
    float* outp = g_scorep + (size_t)ks * BT * VOCAB;
    float acc[8][4];
    #pragma unroll
    for (int r = 0; r < 8; r++)
        #pragma unroll
        for (int j = 0; j < 4; j++) acc[r][j] = 0.f;
    for (int k0 = kbase; k0 < kbase + 128; k0 += 32) {
        __syncthreads();
        for (int i = threadIdx.x; i < 2048; i += 256) {
            int r = i >> 5, kk = i & 31;
            As[r][kk] = g_chat[r * 512 + k0 + kk];
        }
        __syncthreads();
        #pragma unroll 8
        for (int kk = 0; kk < 32; kk++) {
            float4 w;
            if (okfull) {
                w = *reinterpret_cast<const float4*>(&Wmlp[(size_t)(k0 + kk) * VOCAB + c0]);
            } else {
                w.x = (c0     < VOCAB) ? Wmlp[(size_t)(k0 + kk) * VOCAB + c0]     : 0.f;
                w.y = (c0 + 1 < VOCAB) ? Wmlp[(size_t)(k0 + kk) * VOCAB + c0 + 1] : 0.f;
                w.z = (c0 + 2 < VOCAB) ? Wmlp[(size_t)(k0 + kk) * VOCAB + c0 + 2] : 0.f;
                w.w = (c0 + 3 < VOCAB) ? Wmlp[(size_t)(k0 + kk) * VOCAB + c0 + 3] : 0.f;
            }
            #pragma unroll
            for (int r = 0; r < 8; r++) {
                float a = As[rowg * 8 + r][kk];
                acc[r][0] += a * w.x;
                acc[r][1] += a * w.y;
                acc[r][2] += a * w.z;
                acc[r][3] += a * w.w;
            }
        }
    }
    #pragma unroll
    for (int j = 0; j < 4; j++) {
        int c = c0 + j;
        if (c < VOCAB) {
            #pragma unroll
            for (int r = 0; r < 8; r++)
                outp[(size_t)(rowg * 8 + r) * VOCAB + c] = acc[r][j];
        }
    }
}

// ---------------------------------------------------------------------------
// reduce scores: out = sum of 4 partials + bias.  625 x 256, float4.
// ---------------------------------------------------------------------------
__global__ void reduce_scores_kernel(const float* __restrict__ bmlp,
                                     float* __restrict__ out) {
    const int idx = (blockIdx.x * 256 + threadIdx.x) * 4;
    float4 r = {0.f, 0.f, 0.f, 0.f};
    #pragma unroll
    for (int p = 0; p < SKS; p++) {
        const float4 v = *reinterpret_cast<const float4*>(&g_scorep[(size_t)p * BT * VOCAB + idx]);
        r.x += v.x; r.y += v.y; r.z += v.z; r.w += v.w;
    }
    const int c = idx % VOCAB;
    const float4 b = *reinterpret_cast<const float4*>(&bmlp[c]);
    r.x += b.x; r.y += b.y; r.z += b.z; r.w += b.w;
    *reinterpret_cast<float4*>(&out[idx]) = r;
}

// ---------------------------------------------------------------------------
extern "C" void kernel_launch(void* const* d_in, const int* in_sizes, int n_in,
                              void* d_out, int out_size) {
    (void)in_sizes; (void)n_in; (void)out_size;
    const float* x       = (const float*)d_in[0];
    const float* hiddens = (const float*)d_in[1];
    const float* cells   = (const float*)d_in[2];
    const float* V       = (const float*)d_in[3];
    const float* Wsx     = (const float*)d_in[4];
    const float* Wsh     = (const float*)d_in[5];
    const float* Wv      = (const float*)d_in[6];
    const float* Wg      = (const float*)d_in[7];
    const float* Ws      = (const float*)d_in[8];
    const float* Wh      = (const float*)d_in[9];
    const float* Wfeat   = (const float*)d_in[10];
    const float* Wcxt    = (const float*)d_in[11];
    const float* Wg2     = (const float*)d_in[12];
    const float* Wspat   = (const float*)d_in[13];
    const float* Wchan   = (const float*)d_in[14];
    const float* Wgvs    = (const float*)d_in[15];
    const float* Wgvc    = (const float*)d_in[16];
    const float* Wghs    = (const float*)d_in[17];
    const float* Wghc    = (const float*)d_in[18];
    const float* Wmlp    = (const float*)d_in[19];
    const float* bmlp    = (const float*)d_in[20];

    float* out        = (float*)d_out;
    float* out_scores = out;
    float* out_alpha  = out + BT * VOCAB;
    float* out_beta   = out + BT * VOCAB + BT * NPIX;

    bigA_kernel<<<dim3(4, 32, 4), 256>>>(x, hiddens, Wsx, Wsh, Wg2, Wghs, Wghc);
    s_finalize_kernel<<<64, 512>>>(cells);
    cxtgates_kernel<<<512, 256>>>(V, Wfeat, Wcxt, Wgvs, Wgvc);
    smstats_kernel<<<64, 256>>>();
    wfwv_kernel<<<dim3(64, DSPLIT), 64>>>(V, Wv);
    mreduce_kernel<<<601, 256>>>();
    zt_kernel<<<64, 256>>>(hiddens, V, Wg, Ws, Wh, out_alpha, out_beta);
    spatpart_kernel<<<dim3(4, 64), 256>>>(Wspat);
    combine_kernel<<<64, 512>>>(hiddens, Wchan);
    scores_kernel<<<dim3(79, SKS), 256>>>(Wmlp);
    reduce_scores_kernel<<<625, 256>>>(bmlp, out_scores);
}

// round 16
// speedup vs baseline: 1.3015x; 1.3015x over previous
#include <cuda_runtime.h>
#include <math.h>

#define BT    64
#define NPIX  49
#define CDIM  2048
#define VOCAB 10000
#define DSPLIT 16
#define KS    8    // k-split for 512-K GEMMs
#define SKS   4    // k-split for scores

// ---------------- scratch ----------------
__device__ float g_prep[KS*2*BT*512];
__device__ float g_hgatep[KS*2*BT*512];
__device__ float g_sgatep[KS*2*BT*512];
__device__ float g_s[BT*512];
__device__ float g_alpha0[BT*CDIM];
__device__ float g_Mpart[DSPLIT*BT*NPIX*NPIX];
__device__ float g_cchanp[DSPLIT*BT*NPIX];
__device__ float g_cspat[BT*CDIM];
__device__ float g_spart[16*BT*512];
__device__ float g_chat[BT*512];
__device__ float g_scorep[SKS*BT*VOCAB];

__device__ __forceinline__ float tanh_fast(float x) {
    float y;
    asm("tanh.approx.f32 %0, %1;" : "=f"(y) : "f"(x));
    return y;
}
__device__ __forceinline__ float sigmoidf_(float x) {
    return 1.0f / (1.0f + __expf(-x));
}

// ---------------------------------------------------------------------------
// bigA: op0: x@Wsx + hprev@Wsh ; op1: h@Wg2 ; op2: h@Wghs ; op3: h@Wghc.
// grid (4, 32, 4) = 512 blocks, 256 thr; K=64/block; float4 weights.
// ---------------------------------------------------------------------------
__global__ void bigA_kernel(const float* __restrict__ x,
                            const float* __restrict__ hiddens,
                            const float* __restrict__ Wsx,
                            const float* __restrict__ Wsh,
                            const float* __restrict__ Wg2,
                            const float* __restrict__ Wghs,
                            const float* __restrict__ Wghc) {
    __shared__ __align__(16) float As[16][64];
    const int op = blockIdx.z;
    const int ks = blockIdx.y >> 2;
    const int m0 = (blockIdx.y & 3) * 16;
    const int n0 = blockIdx.x * 128;
    const int k0 = ks * 64;
    const int col = n0 + (threadIdx.x & 31) * 4;
    const int rl  = (threadIdx.x >> 5) * 2;
    const int r0  = m0 + rl;
    float4 acc0 = {0.f,0.f,0.f,0.f}, acc1 = {0.f,0.f,0.f,0.f};
    const int nph = (op == 0) ? 2 : 1;
    for (int phase = 0; phase < nph; ++phase) {
        const float* W = (op == 0) ? (phase ? Wsh : Wsx)
                       : (op == 1) ? Wg2 : (op == 2) ? Wghs : Wghc;
        __syncthreads();
        for (int i = threadIdx.x; i < 1024; i += 256) {
            int r = m0 + (i >> 6), kk = i & 63;
            float v;
            if (op == 0 && phase == 1) v = (r & 7) ? hiddens[(r - 1) * 512 + k0 + kk] : 0.f;
            else if (op == 0)          v = x[r * 512 + k0 + kk];
            else                       v = hiddens[r * 512 + k0 + kk];
            As[i >> 6][kk] = v;
        }
        __syncthreads();
        #pragma unroll 8
        for (int kk = 0; kk < 64; kk++) {
            const float4 w = *reinterpret_cast<const float4*>(&W[(size_t)(k0 + kk) * 512 + col]);
            float a0 = As[rl][kk], a1 = As[rl + 1][kk];
            acc0.x += a0 * w.x; acc0.y += a0 * w.y; acc0.z += a0 * w.z; acc0.w += a0 * w.w;
            acc1.x += a1 * w.x; acc1.y += a1 * w.y; acc1.z += a1 * w.z; acc1.w += a1 * w.w;
        }
    }
    float* dst = (op < 2) ? g_prep : g_hgatep;
    const int o2 = op & 1;
    *reinterpret_cast<float4*>(&dst[((ks*2 + o2)*BT + r0)*512 + col])     = acc0;
    *reinterpret_cast<float4*>(&dst[((ks*2 + o2)*BT + r0 + 1)*512 + col]) = acc1;
}

// ---------------------------------------------------------------------------
// s_finalize: g_s = sigmoid(sum partials) * tanh(cells).  64 x 512.
// ---------------------------------------------------------------------------
__global__ void s_finalize_kernel(const float* __restrict__ cells) {
    const int r = blockIdx.x, c = threadIdx.x;
    float p = 0.f;
    #pragma unroll
    for (int ks = 0; ks < KS; ks++) p += g_prep[((ks*2 + 0)*BT + r)*512 + c];
    g_s[r*512 + c] = sigmoidf_(p) * tanh_fast(cells[r*512 + c]);
}

// ---------------------------------------------------------------------------
// cxt: 256 blocks (bt = bx>>2, chunk = bx&3), 256 thr.
// ---------------------------------------------------------------------------
__global__ void cxt_kernel(const float* __restrict__ V,
                           const float* __restrict__ Wfeat,
                           const float* __restrict__ Wcxt) {
    __shared__ __align__(16) float wf[512];
    __shared__ __align__(16) float wc[512];
    __shared__ __align__(16) float gr[512];
    const int bx = blockIdx.x;
    const int t = threadIdx.x;
    const int bt = bx >> 2, b = bt >> 3, chunk = bx & 3;
    for (int i = t; i < 512; i += 256) {
        wf[i] = Wfeat[i];
        wc[i] = Wcxt[i];
        float g = 0.f;
        #pragma unroll
        for (int ks = 0; ks < KS; ks++) g += g_prep[((ks*2 + 1)*BT + bt)*512 + i];
        gr[i] = g;
    }
    const int d0 = chunk * 512 + t;
    float a0s = 0.f, a1s = 0.f;
    #pragma unroll 7
    for (int k = 0; k < NPIX; k++) {
        a0s += V[(b * NPIX + k) * CDIM + d0];
        a1s += V[(b * NPIX + k) * CDIM + d0 + 256];
    }
    const float a0 = a0s * (1.0f / 49.0f);
    const float a1 = a1s * (1.0f / 49.0f);
    __syncthreads();
    float c0 = 0.f, c1 = 0.f;
    #pragma unroll 4
    for (int j = 0; j < 512; j++) {
        float wfj = wf[j], grj = gr[j], wcj = wc[j];
        c0 += tanh_fast(fmaf(a0, wfj, grj)) * wcj;
        c1 += tanh_fast(fmaf(a1, wfj, grj)) * wcj;
    }
    g_alpha0[bt * CDIM + d0]       = c0;
    g_alpha0[bt * CDIM + d0 + 256] = c1;
}

// ---------------------------------------------------------------------------
// gatesS: s@Wgvs (op0), s@Wgvc (op1). grid (4, 32, 2) = 256 blocks, K=64/blk.
// Runs on side stream, overlapped with cxt+wfwv chain.
// ---------------------------------------------------------------------------
__global__ void gatesS_kernel(const float* __restrict__ Wgvs,
                              const float* __restrict__ Wgvc) {
    __shared__ __align__(16) float As[16][64];
    const int op = blockIdx.z;
    const int ks = blockIdx.y >> 2;
    const int m0 = (blockIdx.y & 3) * 16;
    const int n0 = blockIdx.x * 128;
    const int k0 = ks * 64;
    const int col = n0 + (threadIdx.x & 31) * 4;
    const int rl  = (threadIdx.x >> 5) * 2;
    const int r0  = m0 + rl;
    const float* W = op ? Wgvc : Wgvs;
    for (int i = threadIdx.x; i < 1024; i += 256) {
        int r = m0 + (i >> 6), kk = i & 63;
        As[i >> 6][kk] = g_s[r * 512 + k0 + kk];
    }
    __syncthreads();
    float4 acc0 = {0.f,0.f,0.f,0.f}, acc1 = {0.f,0.f,0.f,0.f};
    #pragma unroll 8
    for (int kk = 0; kk < 64; kk++) {
        const float4 w = *reinterpret_cast<const float4*>(&W[(size_t)(k0 + kk) * 512 + col]);
        float a0 = As[rl][kk], a1 = As[rl + 1][kk];
        acc0.x += a0 * w.x; acc0.y += a0 * w.y; acc0.z += a0 * w.z; acc0.w += a0 * w.w;
        acc1.x += a1 * w.x; acc1.y += a1 * w.y; acc1.z += a1 * w.z; acc1.w += a1 * w.w;
    }
    *reinterpret_cast<float4*>(&g_sgatep[((ks*2 + op)*BT + r0)*512 + col])     = acc0;
    *reinterpret_cast<float4*>(&g_sgatep[((ks*2 + op)*BT + r0 + 1)*512 + col]) = acc1;
}

// ---------------------------------------------------------------------------
// wfwv with in-block softmax. grid (64 bt, 16 dp), 192 thr, K=128/blk. (R12)
// ---------------------------------------------------------------------------
__global__ void wfwv_kernel(const float* __restrict__ V,
                            const float* __restrict__ Wv) {
    __shared__ __align__(16) float Wvs[64][52];
    __shared__ __align__(16) float aV[49][65];
    __shared__ __align__(16) float alp[128];
    __shared__ float red[8];
    const int bt = blockIdx.x, b = bt >> 3;
    const int dp = blockIdx.y, d0 = dp * 128;
    const int t = threadIdx.x;
    const int lane = t & 31, w = t >> 5;
    const float* arow = g_alpha0 + bt * CDIM;

    float mx = -1e30f;
    for (int i = t; i < CDIM; i += 192) mx = fmaxf(mx, arow[i]);
    #pragma unroll
    for (int o = 16; o > 0; o >>= 1) mx = fmaxf(mx, __shfl_xor_sync(0xffffffffu, mx, o));
    if (lane == 0) red[w] = mx;
    __syncthreads();
    const float m2 = fmaxf(fmaxf(fmaxf(red[0], red[1]), fmaxf(red[2], red[3])),
                           fmaxf(red[4], red[5]));
    __syncthreads();
    float sm = 0.f;
    for (int i = t; i < CDIM; i += 192) sm += __expf(arow[i] - m2);
    #pragma unroll
    for (int o = 16; o > 0; o >>= 1) sm += __shfl_xor_sync(0xffffffffu, sm, o);
    if (lane == 0) red[w] = sm;
    __syncthreads();
    const float inv = 1.0f / (red[0] + red[1] + red[2] + red[3] + red[4] + red[5]);
    if (t < 128) alp[t] = __expf(arow[d0 + t] - m2) * inv;
    if (t < 64) { Wvs[t][49] = 0.f; Wvs[t][50] = 0.f; Wvs[t][51] = 0.f; }

    const int tk = t / 13, tk2 = t % 13;
    const bool active = (t < 169);
    int ki[4];
    #pragma unroll
    for (int i = 0; i < 4; i++) ki[i] = min(tk * 4 + i, 48);
    float acc[4][4];
    #pragma unroll
    for (int i = 0; i < 4; i++)
        #pragma unroll
        for (int j = 0; j < 4; j++) acc[i][j] = 0.f;
    float chs0 = 0.f, chs1 = 0.f, chs2 = 0.f;
    const int crow = t - 169;
    for (int c = 0; c < 2; c++) {
        __syncthreads();
        for (int i = t; i < 49 * 64; i += 192) {
            int r = i >> 6, dd = i & 63;
            aV[r][dd] = V[(b * NPIX + r) * CDIM + d0 + c * 64 + dd] * alp[c * 64 + dd];
        }
        for (int i = t; i < 64 * 49; i += 192) {
            Wvs[i / 49][i % 49] = Wv[(size_t)(d0 + c * 64) * NPIX + i];
        }
        __syncthreads();
        if (active) {
            #pragma unroll 4
            for (int dd = 0; dd < 64; dd++) {
                const float4 wv = *reinterpret_cast<const float4*>(&Wvs[dd][tk2 * 4]);
                float av0 = aV[ki[0]][dd], av1 = aV[ki[1]][dd];
                float av2 = aV[ki[2]][dd], av3 = aV[ki[3]][dd];
                acc[0][0] += av0 * wv.x; acc[0][1] += av0 * wv.y; acc[0][2] += av0 * wv.z; acc[0][3] += av0 * wv.w;
                acc[1][0] += av1 * wv.x; acc[1][1] += av1 * wv.y; acc[1][2] += av1 * wv.z; acc[1][3] += av1 * wv.w;
                acc[2][0] += av2 * wv.x; acc[2][1] += av2 * wv.y; acc[2][2] += av2 * wv.z; acc[2][3] += av2 * wv.w;
                acc[3][0] += av3 * wv.x; acc[3][1] += av3 * wv.y; acc[3][2] += av3 * wv.z; acc[3][3] += av3 * wv.w;
            }
        } else {
            float s0 = 0.f, s1 = 0.f, s2 = 0.f;
            #pragma unroll 8
            for (int dd = 0; dd < 64; dd++) {
                s0 += aV[crow][dd];
                if (crow + 23 < 49) s1 += aV[crow + 23][dd];
                if (crow + 46 < 49) s2 += aV[crow + 46][dd];
            }
            chs0 += s0; chs1 += s1; chs2 += s2;
        }
    }
    if (active) {
        #pragma unroll
        for (int i = 0; i < 4; i++) {
            int k = tk * 4 + i;
            if (k >= NPIX) continue;
            #pragma unroll
            for (int j = 0; j < 4; j++) {
                int k2 = tk2 * 4 + j;
                if (k2 < NPIX)
                    g_Mpart[(((size_t)dp * BT + bt) * NPIX + k) * NPIX + k2] = acc[i][j];
            }
        }
    } else {
        g_cchanp[(dp * BT + bt) * NPIX + crow] = chs0;
        if (crow + 23 < 49) g_cchanp[(dp * BT + bt) * NPIX + crow + 23] = chs1;
        if (crow + 46 < 49) g_cchanp[(dp * BT + bt) * NPIX + crow + 46] = chs2;
    }
}

// ---------------------------------------------------------------------------
// zt: fused gcs + z_t + softmaxes + c_spatial. grid 64 x 256 thr. (R12)
// ---------------------------------------------------------------------------
__global__ void zt_kernel(const float* __restrict__ hiddens,
                          const float* __restrict__ V,
                          const float* __restrict__ Wg,
                          const float* __restrict__ Ws,
                          const float* __restrict__ Wh,
                          float* __restrict__ out_alpha,
                          float* __restrict__ out_beta) {
    __shared__ float h_sm[512], s_sm[512];
    __shared__ float Msum[NPIX * NPIX];
    __shared__ float pg[8][NPIX], ps[8][NPIX];
    __shared__ float gg[NPIX], css[NPIX], wh[NPIX], ztv[NPIX], al[NPIX];
    const int bt = blockIdx.x, b = bt >> 3, t = threadIdx.x;
    for (int i = t; i < 512; i += 256) {
        h_sm[i] = hiddens[bt * 512 + i];
        s_sm[i] = g_s[bt * 512 + i];
    }
    if (t < NPIX) wh[t] = Wh[t];
    {
        const float* p0 = g_Mpart + (size_t)bt * NPIX * NPIX;
        const size_t stride = (size_t)BT * NPIX * NPIX;
        for (int i = t; i < NPIX * NPIX; i += 256) {
            float v = 0.f;
            #pragma unroll
            for (int p = 0; p < DSPLIT; p++) v += p0[p * stride + i];
            Msum[i] = v;
        }
    }
    __syncthreads();
    {
        const int w = t >> 5, lane = t & 31;
        float gp0 = 0.f, sp0 = 0.f, gp1 = 0.f, sp1 = 0.f;
        const int j1 = lane + 32;
        for (int kk = 0; kk < 64; kk++) {
            int k = w * 64 + kk;
            float hk = h_sm[k], sk = s_sm[k];
            gp0 += hk * Wg[k * NPIX + lane];
            sp0 += sk * Ws[k * NPIX + lane];
            if (j1 < NPIX) {
                gp1 += hk * Wg[k * NPIX + j1];
                sp1 += sk * Ws[k * NPIX + j1];
            }
        }
        pg[w][lane] = gp0; ps[w][lane] = sp0;
        if (j1 < NPIX) { pg[w][j1] = gp1; ps[w][j1] = sp1; }
    }
    __syncthreads();
    if (t < NPIX) {
        float gv = 0.f, sv = 0.f;
        #pragma unroll
        for (int w = 0; w < 8; w++) { gv += pg[w][t]; sv += ps[w][t]; }
        gg[t] = gv;
        css[t] = sv + gv;
    }
    __syncthreads();
    if (t < NPIX) {
        float z = 0.f;
        #pragma unroll 7
        for (int k2 = 0; k2 < NPIX; k2++)
            z += tanh_fast(tanh_fast(Msum[t * NPIX + k2] + gg[k2])) * wh[k2];
        ztv[t] = z;
    }
    __syncthreads();
    if (t == 0) {
        float ze = 0.f;
        for (int k = 0; k < NPIX; k++) ze += tanh_fast(css[k]) * wh[k];
        float mx = -1e30f;
        for (int k = 0; k < NPIX; k++) mx = fmaxf(mx, ztv[k]);
        float sm = 0.f;
        for (int k = 0; k < NPIX; k++) sm += __expf(ztv[k] - mx);
        float inv = 1.0f / sm;
        for (int k = 0; k < NPIX; k++) {
            float a = __expf(ztv[k] - mx) * inv;
            al[k] = a;
            out_alpha[bt * NPIX + k] = a;
        }
        float mx2 = fmaxf(mx, ze);
        float sm2 = 0.f;
        for (int k = 0; k < NPIX; k++) sm2 += __expf(ztv[k] - mx2);
        sm2 += __expf(ze - mx2);
        out_beta[bt] = __expf(ze - mx2) / sm2;
    }
    __syncthreads();
    for (int d = t; d < CDIM; d += 256) {
        float s = 0.f;
        #pragma unroll 7
        for (int k = 0; k < NPIX; k++) s += al[k] * V[(b * NPIX + k) * CDIM + d];
        g_cspat[bt * CDIM + d] = s;
    }
}

// ---------------------------------------------------------------------------
// spatpart: cspat@Wspat partials, K-split 16. grid (4, 64), 256 thr.
// ---------------------------------------------------------------------------
__global__ void spatpart_kernel(const float* __restrict__ Wspat) {
    __shared__ __align__(16) float As[16][64];
    const int ks = blockIdx.y >> 2;
    const int m0 = (blockIdx.y & 3) * 16;
    const int n0 = blockIdx.x * 128;
    const int kbase = ks * 128;
    const int col = n0 + (threadIdx.x & 31) * 4;
    const int rl  = (threadIdx.x >> 5) * 2;
    const int r0  = m0 + rl;
    float4 acc0 = {0.f,0.f,0.f,0.f}, acc1 = {0.f,0.f,0.f,0.f};
    for (int k0 = kbase; k0 < kbase + 128; k0 += 64) {
        __syncthreads();
        for (int i = threadIdx.x; i < 1024; i += 256) {
            int r = m0 + (i >> 6), kk = i & 63;
            As[i >> 6][kk] = g_cspat[r * CDIM + k0 + kk];
        }
        __syncthreads();
        #pragma unroll 8
        for (int kk = 0; kk < 64; kk++) {
            const float4 w = *reinterpret_cast<const float4*>(&Wspat[(size_t)(k0 + kk) * 512 + col]);
            float a0 = As[rl][kk], a1 = As[rl + 1][kk];
            acc0.x += a0 * w.x; acc0.y += a0 * w.y; acc0.z += a0 * w.z; acc0.w += a0 * w.w;
            acc1.x += a1 * w.x; acc1.y += a1 * w.y; acc1.z += a1 * w.z; acc1.w += a1 * w.w;
        }
    }
    *reinterpret_cast<float4*>(&g_spart[(ks * BT + r0) * 512 + col])     = acc0;
    *reinterpret_cast<float4*>(&g_spart[(ks * BT + r0 + 1) * 512 + col]) = acc1;
}

// ---------------------------------------------------------------------------
// combine: chat = sig(gates)*spat + sig(gates)*cchan@Wchan + h.  64 x 512.
// ---------------------------------------------------------------------------
__global__ void combine_kernel(const float* __restrict__ hiddens,
                               const float* __restrict__ Wchan) {
    __shared__ float ch[NPIX];
    const int r = blockIdx.x, c = threadIdx.x;
    if (c < NPIX) {
        float v = 0.f;
        #pragma unroll
        for (int p = 0; p < DSPLIT; p++) v += g_cchanp[(p * BT + r) * NPIX + c];
        ch[c] = v * (1.0f / 2048.0f);
    }
    __syncthreads();
    float spat = 0.f;
    #pragma unroll
    for (int p = 0; p < 16; p++) spat += g_spart[(p * BT + r) * 512 + c];
    float sg = 0.f, cg = 0.f;
    #pragma unroll
    for (int ks = 0; ks < KS; ks++) {
        sg += g_sgatep[((ks*2 + 0)*BT + r)*512 + c] + g_hgatep[((ks*2 + 0)*BT + r)*512 + c];
        cg += g_sgatep[((ks*2 + 1)*BT + r)*512 + c] + g_hgatep[((ks*2 + 1)*BT + r)*512 + c];
    }
    float cb = 0.f;
    #pragma unroll 7
    for (int k = 0; k < NPIX; k++) cb += ch[k] * Wchan[k * 512 + c];
    g_chat[r * 512 + c] = sigmoidf_(sg) * spat
                        + sigmoidf_(cg) * cb
                        + hiddens[r * 512 + c];
}

// ---------------------------------------------------------------------------
// scores partials: grid (79, 4) = 316 blocks, 256 thr, K=128/block.
// ---------------------------------------------------------------------------
__global__ void scores_kernel(const float* __restrict__ Wmlp) {
    __shared__ __align__(16) float As[64][33];
    const int n0 = blockIdx.x * 128;
    const int ks = blockIdx.y;
    const int kbase = ks * 128;
    const int rowg = threadIdx.x >> 5;
    const int colg = threadIdx.x & 31;
    const int c0 = n0 + colg * 4;
    const bool okfull = (c0 + 3 < VOCAB);
    float* outp = g_scorep + (size_t)ks * BT * VOCAB;
    float acc[8][4];
    #pragma unroll
    for (int r = 0; r < 8; r++)
        #pragma unroll
        for (int j = 0; j < 4; j++) acc[r][j] = 0.f;
    for (int k0 = kbase; k0 < kbase + 128; k0 += 32) {
        __syncthreads();
        for (int i = threadIdx.x; i < 2048; i += 256) {
            int r = i >> 5, kk = i & 31;
            As[r][kk] = g_chat[r * 512 + k0 + kk];
        }
        __syncthreads();
        #pragma unroll 8
        for (int kk = 0; kk < 32; kk++) {
            float4 w;
            if (okfull) {
                w = *reinterpret_cast<const float4*>(&Wmlp[(size_t)(k0 + kk) * VOCAB + c0]);
            } else {
                w.x = (c0     < VOCAB) ? Wmlp[(size_t)(k0 + kk) * VOCAB + c0]     : 0.f;
                w.y = (c0 + 1 < VOCAB) ? Wmlp[(size_t)(k0 + kk) * VOCAB + c0 + 1] : 0.f;
                w.z = (c0 + 2 < VOCAB) ? Wmlp[(size_t)(k0 + kk) * VOCAB + c0 + 2] : 0.f;
                w.w = (c0 + 3 < VOCAB) ? Wmlp[(size_t)(k0 + kk) * VOCAB + c0 + 3] : 0.f;
            }
            #pragma unroll
            for (int r = 0; r < 8; r++) {
                float a = As[rowg * 8 + r][kk];
                acc[r][0] += a * w.x;
                acc[r][1] += a * w.y;
                acc[r][2] += a * w.z;
                acc[r][3] += a * w.w;
            }
        }
    }
    #pragma unroll
    for (int j = 0; j < 4; j++) {
        int c = c0 + j;
        if (c < VOCAB) {
            #pragma unroll
            for (int r = 0; r < 8; r++)
                outp[(size_t)(rowg * 8 + r) * VOCAB + c] = acc[r][j];
        }
    }
}

// ---------------------------------------------------------------------------
// reduce scores: out = sum of 4 partials + bias.  625 x 256, float4.
// ---------------------------------------------------------------------------
__global__ void reduce_scores_kernel(const float* __restrict__ bmlp,
                                     float* __restrict__ out) {
    const int idx = (blockIdx.x * 256 + threadIdx.x) * 4;
    float4 r = {0.f, 0.f, 0.f, 0.f};
    #pragma unroll
    for (int p = 0; p < SKS; p++) {
        const float4 v = *reinterpret_cast<const float4*>(&g_scorep[(size_t)p * BT * VOCAB + idx]);
        r.x += v.x; r.y += v.y; r.z += v.z; r.w += v.w;
    }
    const int c = idx % VOCAB;
    const float4 b = *reinterpret_cast<const float4*>(&bmlp[c]);
    r.x += b.x; r.y += b.y; r.z += b.z; r.w += b.w;
    *reinterpret_cast<float4*>(&out[idx]) = r;
}

// ---------------------------------------------------------------------------
extern "C" void kernel_launch(void* const* d_in, const int* in_sizes, int n_in,
                              void* d_out, int out_size) {
    (void)in_sizes; (void)n_in; (void)out_size;
    const float* x       = (const float*)d_in[0];
    const float* hiddens = (const float*)d_in[1];
    const float* cells   = (const float*)d_in[2];
    const float* V       = (const float*)d_in[3];
    const float* Wsx     = (const float*)d_in[4];
    const float* Wsh     = (const float*)d_in[5];
    const float* Wv      = (const float*)d_in[6];
    const float* Wg      = (const float*)d_in[7];
    const float* Ws      = (const float*)d_in[8];
    const float* Wh      = (const float*)d_in[9];
    const float* Wfeat   = (const float*)d_in[10];
    const float* Wcxt    = (const float*)d_in[11];
    const float* Wg2     = (const float*)d_in[12];
    const float* Wspat   = (const float*)d_in[13];
    const float* Wchan   = (const float*)d_in[14];
    const float* Wgvs    = (const float*)d_in[15];
    const float* Wgvc    = (const float*)d_in[16];
    const float* Wghs    = (const float*)d_in[17];
    const float* Wghc    = (const float*)d_in[18];
    const float* Wmlp    = (const float*)d_in[19];
    const float* bmlp    = (const float*)d_in[20];

    float* out        = (float*)d_out;
    float* out_scores = out;
    float* out_alpha  = out + BT * VOCAB;
    float* out_beta   = out + BT * VOCAB + BT * NPIX;

    // Persistent side stream + events for the independent gatesS branch.
    static cudaStream_t s2 = nullptr;
    static cudaEvent_t ev_fork = nullptr, ev_join = nullptr;
    if (s2 == nullptr) {
        cudaStreamCreateWithFlags(&s2, cudaStreamNonBlocking);
        cudaEventCreateWithFlags(&ev_fork, cudaEventDisableTiming);
        cudaEventCreateWithFlags(&ev_join, cudaEventDisableTiming);
    }

    bigA_kernel<<<dim3(4, 32, 4), 256>>>(x, hiddens, Wsx, Wsh, Wg2, Wghs, Wghc);
    s_finalize_kernel<<<64, 512>>>(cells);

    // fork: gatesS depends only on g_s; run it concurrently with cxt/wfwv/zt.
    cudaEventRecord(ev_fork, 0);
    cudaStreamWaitEvent(s2, ev_fork, 0);
    gatesS_kernel<<<dim3(4, 32, 2), 256, 0, s2>>>(Wgvs, Wgvc);
    cudaEventRecord(ev_join, s2);

    cxt_kernel<<<256, 256>>>(V, Wfeat, Wcxt);
    wfwv_kernel<<<dim3(64, DSPLIT), 192>>>(V, Wv);
    zt_kernel<<<64, 256>>>(hiddens, V, Wg, Ws, Wh, out_alpha, out_beta);
    spatpart_kernel<<<dim3(4, 64), 256>>>(Wspat);

    // join before combine (needs g_sgatep)
    cudaStreamWaitEvent(0, ev_join, 0);
    combine_kernel<<<64, 512>>>(hiddens, Wchan);
    scores_kernel<<<dim3(79, SKS), 256>>>(Wmlp);
    reduce_scores_kernel<<<625, 256>>>(bmlp, out_scores);
}